// round 16
// baseline (speedup 1.0000x reference)
#include <cuda_runtime.h>
#include <cuda_bf16.h>
#include <cstdint>

// Problem constants
#define NB_   2
#define SEQ  2048
#define CDIM 1024
#define NH   16
#define HD   64

// ---------------------------------------------------------------------------
// Static device scratch
// ---------------------------------------------------------------------------
#define E_X   ((size_t)NB_ * SEQ * CDIM)      // 4M elems
#define E_WS  ((size_t)SEQ * SEQ)             // 4M
#define E_W   ((size_t)CDIM * CDIM)           // 1M
#define E_P   ((size_t)NB_ * NH * SEQ * SEQ)  // 134M
#define N_RS  ((size_t)NB_ * NH * SEQ)        // 65536 row sums

__device__ __nv_bfloat16 g_xb_h[E_X];
__device__ __nv_bfloat16 g_whs_h[E_WS];
__device__ __nv_bfloat16 g_wqkv_h[3 * E_W];         // q|k|v weights, row-concat
__device__ __nv_bfloat16 g_wo_h[E_WS];
__device__ __nv_bfloat16 g_xh_h[E_X];
__device__ __nv_bfloat16 g_qkv3[3 * E_X];           // dense blocks: q | k | v
__device__ __nv_bfloat16 g_attn[E_P];               // bf16 exp-scores (256 MB)
__device__ __nv_bfloat16 g_z_h[E_X];                // Z dense [b, kj, h*64+d]
__device__ float         g_bqkv[3 * CDIM];
__device__ float         g_rs[N_RS];                // row sums of exp(scores)
__device__ float         g_W1[SEQ + 1];             // colsum of w_hseq + Bsum
__device__ float         g_sxh[(size_t)NB_ * CDIM]; // colsum of xh (fp32)
__device__ float         g_s[(size_t)NB_ * CDIM];   // colsum of v (fp32)

// ---------------------------------------------------------------------------
// Primitives
// ---------------------------------------------------------------------------
__device__ __forceinline__ uint32_t smem_u32(const void* p) {
    uint32_t a;
    asm("{ .reg .u64 t; cvta.to.shared.u64 t, %1; cvt.u32.u64 %0, t; }" : "=r"(a) : "l"(p));
    return a;
}
#define CP16(d, s) asm volatile("cp.async.cg.shared.global [%0], [%1], 16;" :: "r"(d), "l"(s))
#define CP_COMMIT() asm volatile("cp.async.commit_group;" ::: "memory")
#define CP_WAIT1()  asm volatile("cp.async.wait_group 1;" ::: "memory")

__device__ __forceinline__ void ldsm_x4(uint32_t (&r)[4], uint32_t addr) {
    asm volatile("ldmatrix.sync.aligned.m8n8.x4.shared.b16 {%0,%1,%2,%3}, [%4];"
                 : "=r"(r[0]), "=r"(r[1]), "=r"(r[2]), "=r"(r[3]) : "r"(addr));
}
__device__ __forceinline__ void ldsm_x4_t(uint32_t (&r)[4], uint32_t addr) {
    asm volatile("ldmatrix.sync.aligned.m8n8.x4.trans.shared.b16 {%0,%1,%2,%3}, [%4];"
                 : "=r"(r[0]), "=r"(r[1]), "=r"(r[2]), "=r"(r[3]) : "r"(addr));
}
__device__ __forceinline__ void ldsm_x2(uint32_t (&r)[2], uint32_t addr) {
    asm volatile("ldmatrix.sync.aligned.m8n8.x2.shared.b16 {%0,%1}, [%2];"
                 : "=r"(r[0]), "=r"(r[1]) : "r"(addr));
}
__device__ __forceinline__ void ldsm_x2_t(uint32_t (&r)[2], uint32_t addr) {
    asm volatile("ldmatrix.sync.aligned.m8n8.x2.trans.shared.b16 {%0,%1}, [%2];"
                 : "=r"(r[0]), "=r"(r[1]) : "r"(addr));
}
__device__ __forceinline__ void mma16816(float (&c)[4], const uint32_t (&a)[4],
                                         const uint32_t (&b)[2]) {
    asm volatile(
        "mma.sync.aligned.m16n8k16.row.col.f32.bf16.bf16.f32 "
        "{%0,%1,%2,%3}, {%4,%5,%6,%7}, {%8,%9}, {%0,%1,%2,%3};"
        : "+f"(c[0]), "+f"(c[1]), "+f"(c[2]), "+f"(c[3])
        : "r"(a[0]), "r"(a[1]), "r"(a[2]), "r"(a[3]), "r"(b[0]), "r"(b[1]));
}

__device__ __forceinline__ uint32_t pack_bf2(float x0, float x1)
{
    uint32_t r;
    asm("cvt.rn.bf16x2.f32 %0, %1, %2;" : "=r"(r) : "f"(x1), "f"(x0));
    return r;
}

// Fast exp via FMA polynomial (scores are small: sigma ~0.11)
__device__ __forceinline__ float fexp(float x)
{
    float t = x * 1.4426950408889634f;
    float k = rintf(t);
    float f = (t - k) * 0.6931471805599453f;
    float p = 1.0f + f * (1.0f + f * (0.5f + f * (0.166666667f +
                     f * (0.0416666668f + f * 0.00833333340f))));
    return __int_as_float(((int)k + 127) << 23) * p;
}

// ---------------------------------------------------------------------------
// Conversions / small helpers
// ---------------------------------------------------------------------------
__global__ void convert_hi(const float* __restrict__ src,
                           __nv_bfloat16* __restrict__ hi, int n4)
{
    int i = blockIdx.x * blockDim.x + threadIdx.x;
    if (i >= n4) return;
    float4 v = reinterpret_cast<const float4*>(src)[i];
    reinterpret_cast<uint2*>(hi)[i] =
        make_uint2(pack_bf2(v.x, v.y), pack_bf2(v.z, v.w));
}

__global__ void concat_bias(const float* __restrict__ bq, const float* __restrict__ bk,
                            const float* __restrict__ bv, float* __restrict__ o)
{
    int i = blockIdx.x * blockDim.x + threadIdx.x;
    if (i < CDIM) o[i] = bq[i];
    else if (i < 2 * CDIM) o[i] = bk[i - CDIM];
    else if (i < 3 * CDIM) o[i] = bv[i - 2 * CDIM];
}

// ---------------------------------------------------------------------------
// Tensor-core bf16 GEMM (2-stage cp.async pipeline, BK=64).
//   C[m,n] = alpha * sum_k A[m,k]*B[n,k]  (+ bias), fp32 accumulate.
//   OUT=0: fp32 C.  OUT=2: bf16 C.  OUT=3: bf16 exp(alpha*acc) + row sums.
//   OUT=4: bf16 C routed to dense block (n>>10) of Ch (QKV split), ldc=1024.
//   K-major smem pitch 144 B (conflict-free LDSM), trans pitch 272 B.
// ---------------------------------------------------------------------------
template <int TA, int TB, int BIAS, int BN, int OUT, int AP, int BP>
__global__ void __launch_bounds__(256, 2)
tgemm(const __nv_bfloat16* __restrict__ Ah_, const __nv_bfloat16* __restrict__ Al_,
      const __nv_bfloat16* __restrict__ Bh_, const __nv_bfloat16* __restrict__ Bl_,
      float* __restrict__ Cf,
      __nv_bfloat16* __restrict__ Ch, __nv_bfloat16* __restrict__ Cl,
      int lda, int ldb, int ldc,
      long long sAo, long long sAi, long long sBo, long long sBi,
      long long sCo, long long sCi, int zInner,
      const float* __restrict__ bias1, const float* __restrict__ bias2,
      long long sB2o, long long sB2i, float alpha, int K,
      float* __restrict__ rsum)
{
    extern __shared__ char smem[];
    constexpr int BM = 128, BK = 64;
    constexpr int A_SZ = (TA == 0) ? BM * 144 : BK * 272;
    constexpr int A_TOT = (AP ? 2 : 1) * A_SZ;
    constexpr int PB   = (TB == 1) ? 144 : (BN * 2 + 16);
    constexpr int B_SZ = (TB == 1) ? BN * 144 : BK * PB;
    constexpr int B_TOT = (BP ? 2 : 1) * B_SZ;
    constexpr int STAGE = A_TOT + B_TOT;
    constexpr int MI = (BN == 128) ? 4 : 2;
    constexpr int NI = 4;
    constexpr int WM = (BN == 128) ? 2 : 4;

    const int tid = threadIdx.x;
    const int lane = tid & 31, wid = tid >> 5;
    const int m_base = (wid % WM) * MI * 16;
    const int n_base = (wid / WM) * NI * 8;

    int z = blockIdx.z, zo = z / zInner, zi = z % zInner;
    Ah_ += zo * sAo + zi * sAi;
    if (AP) Al_ += zo * sAo + zi * sAi;
    Bh_ += zo * sBo + zi * sBi;
    if (BP) Bl_ += zo * sBo + zi * sBi;
    const long long coff = zo * sCo + zi * sCi;
    if (OUT == 0) Cf += coff; else Ch += coff;
    const float* b2 = (BIAS == 3) ? (bias2 + zo * sB2o + zi * sB2i) : nullptr;

    const int m0 = blockIdx.y * BM;
    const int n0 = blockIdx.x * BN;
    if (OUT == 4) Ch += (size_t)(n0 >> 10) * E_X;

    const uint32_t sb0 = smem_u32(smem);

    auto stage_in = [&](int c, uint32_t base) {
        const int k0 = c * BK;
        if (TA == 0) {
            // 128 rows x 8 segs(16B) = 1024 cp / 256 thr = 4 iters
#pragma unroll
            for (int it = 0; it < 4; ++it) {
                int idx = tid + it * 256, r = idx >> 3, sg = idx & 7;
                uint32_t d = base + r * 144 + sg * 16;
                long long o = (long long)(m0 + r) * lda + k0 + sg * 8;
                CP16(d, Ah_ + o);
                if (AP) CP16(d + A_SZ, Al_ + o);
            }
        } else {
            // 64 k-rows x 16 segs = 1024 -> 4 iters
#pragma unroll
            for (int it = 0; it < 4; ++it) {
                int idx = tid + it * 256, kr = idx >> 4, sg = idx & 15;
                uint32_t d = base + kr * 272 + sg * 16;
                long long o = (long long)(k0 + kr) * lda + m0 + sg * 8;
                CP16(d, Ah_ + o);
                if (AP) CP16(d + A_SZ, Al_ + o);
            }
        }
        if (TB == 1) {
#pragma unroll
            for (int it = 0; it < (BN * 8) / 256; ++it) {
                int idx = tid + it * 256, r = idx >> 3, sg = idx & 7;
                uint32_t d = base + A_TOT + r * 144 + sg * 16;
                long long o = (long long)(n0 + r) * ldb + k0 + sg * 8;
                CP16(d, Bh_ + o);
                if (BP) CP16(d + B_SZ, Bl_ + o);
            }
        } else {
            constexpr int SEGS = BN / 8;
#pragma unroll
            for (int it = 0; it < (BK * SEGS) / 256; ++it) {
                int idx = tid + it * 256, kr = idx / SEGS, sg = idx % SEGS;
                uint32_t d = base + A_TOT + kr * PB + sg * 16;
                long long o = (long long)(k0 + kr) * ldb + n0 + sg * 8;
                CP16(d, Bh_ + o);
                if (BP) CP16(d + B_SZ, Bl_ + o);
            }
        }
    };

    float acc[MI][NI][4] = {};

    const int nch = K / BK;
    stage_in(0, sb0);
    CP_COMMIT();

    for (int c = 0; c < nch; ++c) {
        if (c + 1 < nch) stage_in(c + 1, sb0 + ((c + 1) & 1) * STAGE);
        CP_COMMIT();
        CP_WAIT1();
        __syncthreads();

        const uint32_t ab = sb0 + (c & 1) * STAGE;
        const uint32_t bb = ab + A_TOT;
#pragma unroll
        for (int ks = 0; ks < 4; ++ks) {
            const int kk = ks * 16;
            uint32_t bh[NI][2], bl[NI][2];
#pragma unroll
            for (int ni = 0; ni < NI; ++ni) {
                uint32_t addr;
                if (TB == 1) {
                    addr = bb + (n_base + ni * 8 + (lane & 7)) * 144 + (kk + ((lane >> 3) & 1) * 8) * 2;
                    ldsm_x2(bh[ni], addr);
                    if (BP) ldsm_x2(bl[ni], addr + B_SZ);
                } else {
                    addr = bb + (kk + (lane & 15)) * PB + (n_base + ni * 8) * 2;
                    ldsm_x2_t(bh[ni], addr);
                    if (BP) ldsm_x2_t(bl[ni], addr + B_SZ);
                }
            }
#pragma unroll
            for (int mi = 0; mi < MI; ++mi) {
                uint32_t ah[4], al[4], ad;
                if (TA == 0) {
                    ad = ab + (m_base + mi * 16 + (lane & 15)) * 144 + (kk + (lane >> 4) * 8) * 2;
                    ldsm_x4(ah, ad);
                    if (AP) ldsm_x4(al, ad + A_SZ);
                } else {
                    ad = ab + (kk + (lane & 7) + (lane >> 4) * 8) * 272
                            + (m_base + mi * 16 + ((lane >> 3) & 1) * 8) * 2;
                    ldsm_x4_t(ah, ad);
                    if (AP) ldsm_x4_t(al, ad + A_SZ);
                }
#pragma unroll
                for (int ni = 0; ni < NI; ++ni) {
                    mma16816(acc[mi][ni], ah, bh[ni]);
                    if (BP) mma16816(acc[mi][ni], ah, bl[ni]);
                    if (AP) mma16816(acc[mi][ni], al, bh[ni]);
                }
            }
        }
        __syncthreads();
    }

    // ---- epilogue ----
    if (OUT == 3) {
        float* rs = rsum + (long long)blockIdx.z * ((long long)gridDim.y * BM);
#pragma unroll
        for (int mi = 0; mi < MI; ++mi) {
            int m = m0 + m_base + mi * 16 + (lane >> 2);
            float ra = 0.f, rb = 0.f;
#pragma unroll
            for (int ni = 0; ni < NI; ++ni) {
                int n = n0 + n_base + ni * 8 + 2 * (lane & 3);
                float e0 = fexp(acc[mi][ni][0] * alpha);
                float e1 = fexp(acc[mi][ni][1] * alpha);
                float e2 = fexp(acc[mi][ni][2] * alpha);
                float e3 = fexp(acc[mi][ni][3] * alpha);
                *reinterpret_cast<uint32_t*>(&Ch[(long long)m * ldc + n]) = pack_bf2(e0, e1);
                *reinterpret_cast<uint32_t*>(&Ch[(long long)(m + 8) * ldc + n]) = pack_bf2(e2, e3);
                ra += e0 + e1;
                rb += e2 + e3;
            }
            ra += __shfl_xor_sync(0xffffffffu, ra, 1);
            ra += __shfl_xor_sync(0xffffffffu, ra, 2);
            rb += __shfl_xor_sync(0xffffffffu, rb, 1);
            rb += __shfl_xor_sync(0xffffffffu, rb, 2);
            if ((lane & 3) == 0) {
                atomicAdd(&rs[m], ra);
                atomicAdd(&rs[m + 8], rb);
            }
        }
        return;
    }

#pragma unroll
    for (int mi = 0; mi < MI; ++mi) {
#pragma unroll
        for (int ni = 0; ni < NI; ++ni) {
            int m = m0 + m_base + mi * 16 + (lane >> 2);
            int n = n0 + n_base + ni * 8 + 2 * (lane & 3);
            float v0 = acc[mi][ni][0] * alpha, v1 = acc[mi][ni][1] * alpha;
            float v2 = acc[mi][ni][2] * alpha, v3 = acc[mi][ni][3] * alpha;
            if (BIAS == 1) { float b = bias1[m], bb8 = bias1[m + 8]; v0 += b; v1 += b; v2 += bb8; v3 += bb8; }
            if (BIAS == 2) { float b = bias1[n], bb1 = bias1[n + 1]; v0 += b; v1 += bb1; v2 += b; v3 += bb1; }
            if (BIAS == 3) {
                float c0 = b2[n], c1 = b2[n + 1];
                float bm = bias1[m], bm8 = bias1[m + 8];
                v0 += bm * c0; v1 += bm * c1; v2 += bm8 * c0; v3 += bm8 * c1;
            }
            if (OUT == 0) {
                *reinterpret_cast<float2*>(&Cf[(long long)m * ldc + n]) = make_float2(v0, v1);
                *reinterpret_cast<float2*>(&Cf[(long long)(m + 8) * ldc + n]) = make_float2(v2, v3);
            } else if (OUT == 4) {
                int col = n & (CDIM - 1);
                *reinterpret_cast<uint32_t*>(&Ch[(long long)m * CDIM + col]) = pack_bf2(v0, v1);
                *reinterpret_cast<uint32_t*>(&Ch[(long long)(m + 8) * CDIM + col]) = pack_bf2(v2, v3);
            } else {
                *reinterpret_cast<uint32_t*>(&Ch[(long long)m * ldc + n]) = pack_bf2(v0, v1);
                *reinterpret_cast<uint32_t*>(&Ch[(long long)(m + 8) * ldc + n]) = pack_bf2(v2, v3);
            }
        }
    }
}

// ---------------------------------------------------------------------------
// Attn helpers
// ---------------------------------------------------------------------------
// vh[b,q,c] *= 1/rs[b, c/64, q]  (reciprocal inline; rs stays L2-hot)
__global__ void scale_v(__nv_bfloat16* __restrict__ v, const float* __restrict__ rs)
{
    int i = blockIdx.x * 256 + threadIdx.x;          // word index, E_X/2 total
    int e0 = 2 * i;
    int c = e0 & (CDIM - 1);
    int bq = e0 >> 10;
    int b = bq >> 11, q = bq & (SEQ - 1);
    int h = c >> 6;
    float iz = __fdividef(1.0f, rs[(((long long)b * NH + h) << 11) + q]);
    uint32_t u = reinterpret_cast<uint32_t*>(v)[i];
    float x0 = __uint_as_float(u << 16) * iz;
    float x1 = __uint_as_float(u & 0xffff0000u) * iz;
    reinterpret_cast<uint32_t*>(v)[i] = pack_bf2(x0, x1);
}

// ---------------------------------------------------------------------------
// Analytic-S helper chain (parallel, atomic-merged)
// ---------------------------------------------------------------------------
__global__ void zero_ws(float* __restrict__ W1, float* __restrict__ sxh,
                        float* __restrict__ rs)
{
    int i = blockIdx.x * blockDim.x + threadIdx.x;
    if (i <= SEQ) W1[i] = 0.f;
    if (i < NB_ * CDIM) sxh[i] = 0.f;
    if (i < (int)N_RS) rs[i] = 0.f;
}

__global__ void rowsum_w_at(const float* __restrict__ w, float* __restrict__ W1)
{
    int s = blockIdx.x * 256 + threadIdx.x;
    int t0 = blockIdx.y * 128;
    const float* p = w + (long long)t0 * SEQ + s;
    float acc = 0.f;
#pragma unroll 8
    for (int t = 0; t < 128; t++) acc += p[(long long)t * SEQ];
    atomicAdd(&W1[s], acc);
}

__global__ void sum_bias(const float* __restrict__ b, float* __restrict__ W1)
{
    __shared__ float red[256];
    float acc = 0.f;
    for (int i = threadIdx.x; i < SEQ; i += 256) acc += b[i];
    red[threadIdx.x] = acc;
    __syncthreads();
    for (int o = 128; o; o >>= 1) {
        if (threadIdx.x < o) red[threadIdx.x] += red[threadIdx.x + o];
        __syncthreads();
    }
    if (threadIdx.x == 0) W1[SEQ] = red[0];
}

__global__ void sxh_from_x_at(const float* __restrict__ x, const float* __restrict__ W1,
                              float* __restrict__ sxh)
{
    int idx = blockIdx.x * 256 + threadIdx.x;
    int b = idx >> 10, c = idx & (CDIM - 1);
    int s0 = blockIdx.y * 128;
    const float* xp = x + (long long)b * SEQ * CDIM + (long long)s0 * CDIM + c;
    const float* wp = W1 + s0;
    float acc = 0.f;
#pragma unroll 8
    for (int s = 0; s < 128; s++) acc += wp[s] * xp[(long long)s * CDIM];
    atomicAdd(&sxh[idx], acc);
}

__global__ void add_bsum(float* __restrict__ sxh, const float* __restrict__ W1)
{
    int i = blockIdx.x * blockDim.x + threadIdx.x;
    if (i < NB_ * CDIM) sxh[i] += W1[SEQ];
}

__global__ void s_from_xh(const float* __restrict__ sxh,
                          const float* __restrict__ wv,
                          const float* __restrict__ bv,
                          float* __restrict__ s)
{
    int o = blockIdx.x * 8 + (threadIdx.x >> 5);
    int lane = threadIdx.x & 31;
    int b = o >> 10, cp = o & (CDIM - 1);
    const float* xr = sxh + (long long)b * CDIM;
    const float* wr = wv + (long long)cp * CDIM;
    float acc = 0.f;
#pragma unroll 8
    for (int c = lane; c < CDIM; c += 32) acc += xr[c] * wr[c];
#pragma unroll
    for (int off = 16; off; off >>= 1) acc += __shfl_xor_sync(0xffffffffu, acc, off);
    if (lane == 0) s[o] = acc + (float)SEQ * bv[cp];
}

// ---------------------------------------------------------------------------
// Launch
// ---------------------------------------------------------------------------
extern "C" void kernel_launch(void* const* d_in, const int* in_sizes, int n_in,
                              void* d_out, int out_size)
{
    const float* x      = (const float*)d_in[0];
    const float* w_hseq = (const float*)d_in[1];
    const float* b_hseq = (const float*)d_in[2];
    const float* wq     = (const float*)d_in[3];
    const float* bq     = (const float*)d_in[4];
    const float* wk     = (const float*)d_in[5];
    const float* bk     = (const float*)d_in[6];
    const float* wv     = (const float*)d_in[7];
    const float* bv     = (const float*)d_in[8];
    const float* w_oseq = (const float*)d_in[9];
    const float* b_oseq = (const float*)d_in[10];
    float* out = (float*)d_out;

    __nv_bfloat16 *xbh, *whh, *wqkvh, *woh, *xhh, *qkv3, *zh, *attn;
    float *sv, *sxh, *W1, *rs, *bqkv;
    cudaGetSymbolAddress((void**)&xbh,   g_xb_h);
    cudaGetSymbolAddress((void**)&whh,   g_whs_h);
    cudaGetSymbolAddress((void**)&wqkvh, g_wqkv_h);
    cudaGetSymbolAddress((void**)&woh,   g_wo_h);
    cudaGetSymbolAddress((void**)&xhh,   g_xh_h);
    cudaGetSymbolAddress((void**)&qkv3,  g_qkv3);
    cudaGetSymbolAddress((void**)&zh,    g_z_h);
    cudaGetSymbolAddress((void**)&attn,  g_attn);
    cudaGetSymbolAddress((void**)&bqkv,  g_bqkv);
    cudaGetSymbolAddress((void**)&rs,    g_rs);
    cudaGetSymbolAddress((void**)&W1,    g_W1);
    cudaGetSymbolAddress((void**)&sxh,   g_sxh);
    cudaGetSymbolAddress((void**)&sv,    g_s);

    __nv_bfloat16* qh = qkv3;
    __nv_bfloat16* kh = qkv3 + E_X;
    __nv_bfloat16* vh = qkv3 + 2 * E_X;

    const long long sBT = (long long)SEQ * CDIM;
    const long long sAh_ = (long long)SEQ * SEQ;
    const long long sAb = (long long)NH * SEQ * SEQ;

    // smem: 2 stages of (A_TOT + B_TOT), BK=64
    const int SM_A = 2 * (128 * 144 + 64 * 272);   // 71680  <0,0,1,128,2,0,0>
    const int SM_B = 2 * (128 * 144 + 128 * 144);  // 73728  <0,1,2,128,4>/<C>
    const int SM_E = 2 * (64 * 272 + 64 * 144);    // 53248  <1,0,0,64,2,0,0>
    const int SM_F = 2 * (128 * 144 + 64 * 272);   // 71680  <0,0,3,128,0,0,0>

    cudaFuncSetAttribute(tgemm<0, 0, 1, 128, 2, 0, 0>, cudaFuncAttributeMaxDynamicSharedMemorySize, SM_A);
    cudaFuncSetAttribute(tgemm<0, 1, 2, 128, 4, 0, 0>, cudaFuncAttributeMaxDynamicSharedMemorySize, SM_B);
    cudaFuncSetAttribute(tgemm<0, 1, 0, 128, 3, 0, 0>, cudaFuncAttributeMaxDynamicSharedMemorySize, SM_B);
    cudaFuncSetAttribute(tgemm<1, 0, 0, 64, 2, 0, 0>,  cudaFuncAttributeMaxDynamicSharedMemorySize, SM_E);
    cudaFuncSetAttribute(tgemm<0, 0, 3, 128, 0, 0, 0>, cudaFuncAttributeMaxDynamicSharedMemorySize, SM_F);

    // Converts
    convert_hi<<<(int)(E_X / 4 / 256), 256>>>(x, xbh, (int)(E_X / 4));
    convert_hi<<<(int)(E_WS / 4 / 256), 256>>>(w_hseq, whh, (int)(E_WS / 4));
    convert_hi<<<(int)(E_W / 4 / 256), 256>>>(wq, wqkvh, (int)(E_W / 4));
    convert_hi<<<(int)(E_W / 4 / 256), 256>>>(wk, wqkvh + E_W, (int)(E_W / 4));
    convert_hi<<<(int)(E_W / 4 / 256), 256>>>(wv, wqkvh + 2 * E_W, (int)(E_W / 4));

    // Stage A: xh = w_hseq @ x + b_hseq  (1-pass, hi-only out)
    tgemm<0, 0, 1, 128, 2, 0, 0><<<dim3(CDIM / 128, SEQ / 128, NB_), 256, SM_A>>>(
        whh, nullptr, xbh, nullptr, nullptr, xhh, nullptr,
        SEQ, CDIM, CDIM, 0, 0, sBT, 0, sBT, 0, 1,
        b_hseq, nullptr, 0, 0, 1.0f, SEQ, nullptr);

    // Remaining convert + bias concat + S helper chain
    convert_hi<<<(int)(E_WS / 4 / 256), 256>>>(w_oseq, woh, (int)(E_WS / 4));
    concat_bias<<<12, 256>>>(bq, bk, bv, bqkv);
    zero_ws<<<(int)(N_RS / 256), 256>>>(W1, sxh, rs);
    rowsum_w_at<<<dim3(SEQ / 256, SEQ / 128), 256>>>(w_hseq, W1);
    sum_bias<<<1, 256>>>(b_hseq, W1);
    sxh_from_x_at<<<dim3((NB_ * CDIM) / 256, SEQ / 128), 256>>>(x, W1, sxh);
    add_bsum<<<(NB_ * CDIM + 255) / 256, 256>>>(sxh, W1);
    s_from_xh<<<(NB_ * CDIM) / 8, 256>>>(sxh, wv, bv, sv);

    // Stage B (merged QKV, dense split outputs): q|k|v = xh @ wqkv^T + bqkv
    tgemm<0, 1, 2, 128, 4, 0, 0><<<dim3(3 * CDIM / 128, (NB_ * SEQ) / 128, 1), 256, SM_B>>>(
        xhh, nullptr, wqkvh, nullptr, nullptr, qkv3, nullptr,
        CDIM, CDIM, CDIM, 0, 0, 0, 0, 0, 0, 1,
        bqkv, nullptr, 0, 0, 1.0f, CDIM, nullptr);

    // Stage C: e = exp((1/8) q.k) -> bf16, + row sums (atomic); single K-chunk
    tgemm<0, 1, 0, 128, 3, 0, 0><<<dim3(SEQ / 128, SEQ / 128, NB_ * NH), 256, SM_B>>>(
        qh, nullptr, kh, nullptr, nullptr, attn, nullptr,
        CDIM, CDIM, SEQ, sBT, HD, sBT, HD, sAb, sAh_, NH,
        nullptr, nullptr, 0, 0, 0.125f, HD, rs);

    // Fold softmax normalization into V:  v' = v / Zrow (reciprocal inline)
    scale_v<<<(int)(E_X / 2 / 256), 256>>>(vh, rs);

    // Stage E: Z[b, kj, h*64+d] = sum_q e[q,kj] * v'[q, h*64+d]  (dense Z)
    tgemm<1, 0, 0, 64, 2, 0, 0><<<dim3(1, SEQ / 128, NB_ * NH), 256, SM_E>>>(
        attn, nullptr, vh, nullptr, nullptr, zh, nullptr,
        SEQ, CDIM, CDIM, sAb, sAh_, sBT, HD, sBT, HD, NH,
        nullptr, nullptr, 0, 0, 1.0f, SEQ, nullptr);

    // Stage F: out[b] = wo @ Z[b] + b_oseq (x) S[b]   (batch-2 dense GEMM)
    tgemm<0, 0, 3, 128, 0, 0, 0><<<dim3(CDIM / 128, SEQ / 128, NB_), 256, SM_F>>>(
        woh, nullptr, zh, nullptr, out, nullptr, nullptr,
        SEQ, CDIM, CDIM, 0, 0, sBT, 0, sBT, 0, 1,
        b_oseq, sv, CDIM, 0, 1.0f, SEQ, nullptr);
}

// round 17
// speedup vs baseline: 1.0106x; 1.0106x over previous
#include <cuda_runtime.h>
#include <cuda_bf16.h>
#include <cstdint>

// Problem constants
#define NB_   2
#define SEQ  2048
#define CDIM 1024
#define NH   16
#define HD   64

// ---------------------------------------------------------------------------
// Static device scratch
// ---------------------------------------------------------------------------
#define E_X   ((size_t)NB_ * SEQ * CDIM)      // 4M elems
#define E_WS  ((size_t)SEQ * SEQ)             // 4M
#define E_W   ((size_t)CDIM * CDIM)           // 1M
#define E_P   ((size_t)NB_ * NH * SEQ * SEQ)  // 134M
#define N_RS  ((size_t)NB_ * NH * SEQ)        // 65536 row sums

__device__ __nv_bfloat16 g_xb_h[E_X];
__device__ __nv_bfloat16 g_whs_h[E_WS];
__device__ __nv_bfloat16 g_wqkv_h[3 * E_W];         // q|k|v weights, row-concat
__device__ __nv_bfloat16 g_wo_h[E_WS];
__device__ __nv_bfloat16 g_xh_h[E_X];
__device__ __nv_bfloat16 g_qkv3[3 * E_X];           // dense blocks: q | k | v
__device__ __nv_bfloat16 g_attn[E_P];               // bf16 exp-scores (256 MB)
__device__ __nv_bfloat16 g_z_h[E_X];                // Z dense [b, kj, h*64+d]
__device__ float         g_bqkv[3 * CDIM];
__device__ float         g_rs[N_RS];                // row sums of exp(scores)
__device__ float         g_W1[SEQ + 1];             // colsum of w_hseq + Bsum
__device__ float         g_sxh[(size_t)NB_ * CDIM]; // colsum of xh (fp32)
__device__ float         g_s[(size_t)NB_ * CDIM];   // colsum of v (fp32)

// ---------------------------------------------------------------------------
// Primitives
// ---------------------------------------------------------------------------
__device__ __forceinline__ uint32_t smem_u32(const void* p) {
    uint32_t a;
    asm("{ .reg .u64 t; cvta.to.shared.u64 t, %1; cvt.u32.u64 %0, t; }" : "=r"(a) : "l"(p));
    return a;
}
#define CP16(d, s) asm volatile("cp.async.cg.shared.global [%0], [%1], 16;" :: "r"(d), "l"(s))
#define CP_COMMIT() asm volatile("cp.async.commit_group;" ::: "memory")
#define CP_WAIT1()  asm volatile("cp.async.wait_group 1;" ::: "memory")

__device__ __forceinline__ void ldsm_x4(uint32_t (&r)[4], uint32_t addr) {
    asm volatile("ldmatrix.sync.aligned.m8n8.x4.shared.b16 {%0,%1,%2,%3}, [%4];"
                 : "=r"(r[0]), "=r"(r[1]), "=r"(r[2]), "=r"(r[3]) : "r"(addr));
}
__device__ __forceinline__ void ldsm_x4_t(uint32_t (&r)[4], uint32_t addr) {
    asm volatile("ldmatrix.sync.aligned.m8n8.x4.trans.shared.b16 {%0,%1,%2,%3}, [%4];"
                 : "=r"(r[0]), "=r"(r[1]), "=r"(r[2]), "=r"(r[3]) : "r"(addr));
}
__device__ __forceinline__ void ldsm_x2_t(uint32_t (&r)[2], uint32_t addr) {
    asm volatile("ldmatrix.sync.aligned.m8n8.x2.trans.shared.b16 {%0,%1}, [%2];"
                 : "=r"(r[0]), "=r"(r[1]) : "r"(addr));
}
__device__ __forceinline__ void mma16816(float (&c)[4], const uint32_t (&a)[4],
                                         const uint32_t (&b)[2]) {
    asm volatile(
        "mma.sync.aligned.m16n8k16.row.col.f32.bf16.bf16.f32 "
        "{%0,%1,%2,%3}, {%4,%5,%6,%7}, {%8,%9}, {%0,%1,%2,%3};"
        : "+f"(c[0]), "+f"(c[1]), "+f"(c[2]), "+f"(c[3])
        : "r"(a[0]), "r"(a[1]), "r"(a[2]), "r"(a[3]), "r"(b[0]), "r"(b[1]));
}

__device__ __forceinline__ uint32_t pack_bf2(float x0, float x1)
{
    uint32_t r;
    asm("cvt.rn.bf16x2.f32 %0, %1, %2;" : "=r"(r) : "f"(x1), "f"(x0));
    return r;
}

// Fast exp via FMA polynomial (scores are small: sigma ~0.11)
__device__ __forceinline__ float fexp(float x)
{
    float t = x * 1.4426950408889634f;
    float k = rintf(t);
    float f = (t - k) * 0.6931471805599453f;
    float p = 1.0f + f * (1.0f + f * (0.5f + f * (0.166666667f +
                     f * (0.0416666668f + f * 0.00833333340f))));
    return __int_as_float(((int)k + 127) << 23) * p;
}

// ---------------------------------------------------------------------------
// Conversions / small helpers
// ---------------------------------------------------------------------------
__global__ void convert_hi(const float* __restrict__ src,
                           __nv_bfloat16* __restrict__ hi, int n4)
{
    int i = blockIdx.x * blockDim.x + threadIdx.x;
    if (i >= n4) return;
    float4 v = reinterpret_cast<const float4*>(src)[i];
    reinterpret_cast<uint2*>(hi)[i] =
        make_uint2(pack_bf2(v.x, v.y), pack_bf2(v.z, v.w));
}

__global__ void concat_bias(const float* __restrict__ bq, const float* __restrict__ bk,
                            const float* __restrict__ bv, float* __restrict__ o)
{
    int i = blockIdx.x * blockDim.x + threadIdx.x;
    if (i < CDIM) o[i] = bq[i];
    else if (i < 2 * CDIM) o[i] = bk[i - CDIM];
    else if (i < 3 * CDIM) o[i] = bv[i - 2 * CDIM];
}

// Fused: convert w_hseq -> bf16 AND accumulate column sums into W1.
// grid (SEQ/256, SEQ/128); thread owns column s over a 128-row t-chunk.
__global__ void convert_rowsum_w(const float* __restrict__ w,
                                 __nv_bfloat16* __restrict__ wh,
                                 float* __restrict__ W1)
{
    int s = blockIdx.x * 256 + threadIdx.x;
    int t0 = blockIdx.y * 128;
    const float* p = w + (long long)t0 * SEQ + s;
    __nv_bfloat16* o = wh + (long long)t0 * SEQ + s;
    float acc = 0.f;
#pragma unroll 8
    for (int t = 0; t < 128; t++) {
        float v = p[(long long)t * SEQ];
        acc += v;
        o[(long long)t * SEQ] = __float2bfloat16(v);
    }
    atomicAdd(&W1[s], acc);
}

// Fused: convert x -> bf16 AND accumulate sxh[b,c] += W1[s]*x[b,s,c].
// grid (NB*CDIM/256, SEQ/128). Requires W1 complete.
__global__ void convert_x_sxh(const float* __restrict__ x, const float* __restrict__ W1,
                              __nv_bfloat16* __restrict__ xh,
                              float* __restrict__ sxh)
{
    int idx = blockIdx.x * 256 + threadIdx.x;
    int b = idx >> 10, c = idx & (CDIM - 1);
    int s0 = blockIdx.y * 128;
    long long base = (long long)b * SEQ * CDIM + (long long)s0 * CDIM + c;
    const float* xp = x + base;
    __nv_bfloat16* op = xh + base;
    const float* wp = W1 + s0;
    float acc = 0.f;
#pragma unroll 8
    for (int s = 0; s < 128; s++) {
        float v = xp[(long long)s * CDIM];
        acc += wp[s] * v;
        op[(long long)s * CDIM] = __float2bfloat16(v);
    }
    atomicAdd(&sxh[idx], acc);
}

// ---------------------------------------------------------------------------
// Tensor-core bf16 GEMM (2-stage cp.async pipeline, BK=32).
//   C[m,n] = alpha * sum_k A[m,k]*B[n,k]  (+ bias), fp32 accumulate.
//   OUT=0: fp32 C.  OUT=2: bf16 C.  OUT=3: bf16 exp(alpha*acc) + row sums.
//   OUT=4: bf16 C routed to dense block (n>>10) of Ch (QKV split), ldc=1024.
// ---------------------------------------------------------------------------
template <int TA, int TB, int BIAS, int BN, int OUT, int AP, int BP>
__global__ void __launch_bounds__(256, 2)
tgemm(const __nv_bfloat16* __restrict__ Ah_, const __nv_bfloat16* __restrict__ Al_,
      const __nv_bfloat16* __restrict__ Bh_, const __nv_bfloat16* __restrict__ Bl_,
      float* __restrict__ Cf,
      __nv_bfloat16* __restrict__ Ch, __nv_bfloat16* __restrict__ Cl,
      int lda, int ldb, int ldc,
      long long sAo, long long sAi, long long sBo, long long sBi,
      long long sCo, long long sCi, int zInner,
      const float* __restrict__ bias1, const float* __restrict__ bias2,
      long long sB2o, long long sB2i, float alpha, int K,
      float* __restrict__ rsum)
{
    extern __shared__ char smem[];
    constexpr int BM = 128, BK = 32;
    constexpr int A_SZ = (TA == 0) ? BM * 80 : BK * 272;
    constexpr int A_TOT = (AP ? 2 : 1) * A_SZ;
    constexpr int PB   = (TB == 1) ? 80 : (BN * 2 + 16);
    constexpr int B_SZ = (TB == 1) ? BN * 80 : BK * PB;
    constexpr int B_TOT = (BP ? 2 : 1) * B_SZ;
    constexpr int STAGE = A_TOT + B_TOT;
    constexpr int MI = (BN == 128) ? 4 : 2;
    constexpr int NI = 4;
    constexpr int WM = (BN == 128) ? 2 : 4;

    const int tid = threadIdx.x;
    const int lane = tid & 31, wid = tid >> 5;
    const int m_base = (wid % WM) * MI * 16;
    const int n_base = (wid / WM) * NI * 8;

    int z = blockIdx.z, zo = z / zInner, zi = z % zInner;
    Ah_ += zo * sAo + zi * sAi;
    if (AP) Al_ += zo * sAo + zi * sAi;
    Bh_ += zo * sBo + zi * sBi;
    if (BP) Bl_ += zo * sBo + zi * sBi;
    const long long coff = zo * sCo + zi * sCi;
    if (OUT == 0) Cf += coff; else Ch += coff;
    const float* b2 = (BIAS == 3) ? (bias2 + zo * sB2o + zi * sB2i) : nullptr;

    const int m0 = blockIdx.y * BM;
    const int n0 = blockIdx.x * BN;
    if (OUT == 4) Ch += (size_t)(n0 >> 10) * E_X;

    const uint32_t sb0 = smem_u32(smem);

    auto stage_in = [&](int c, uint32_t base) {
        const int k0 = c * BK;
        if (TA == 0) {
#pragma unroll
            for (int it = 0; it < (BM * 4) / 256; ++it) {
                int idx = tid + it * 256, r = idx >> 2, sg = idx & 3;
                uint32_t d = base + r * 80 + sg * 16;
                long long o = (long long)(m0 + r) * lda + k0 + sg * 8;
                CP16(d, Ah_ + o);
                if (AP) CP16(d + A_SZ, Al_ + o);
            }
        } else {
#pragma unroll
            for (int it = 0; it < (BK * 16) / 256; ++it) {
                int idx = tid + it * 256, kr = idx >> 4, sg = idx & 15;
                uint32_t d = base + kr * 272 + sg * 16;
                long long o = (long long)(k0 + kr) * lda + m0 + sg * 8;
                CP16(d, Ah_ + o);
                if (AP) CP16(d + A_SZ, Al_ + o);
            }
        }
        if (TB == 1) {
#pragma unroll
            for (int it = 0; it < (BN * 4) / 256; ++it) {
                int idx = tid + it * 256, r = idx >> 2, sg = idx & 3;
                uint32_t d = base + A_TOT + r * 80 + sg * 16;
                long long o = (long long)(n0 + r) * ldb + k0 + sg * 8;
                CP16(d, Bh_ + o);
                if (BP) CP16(d + B_SZ, Bl_ + o);
            }
        } else {
            constexpr int SEGS = BN / 8;
#pragma unroll
            for (int it = 0; it < (BK * SEGS) / 256; ++it) {
                int idx = tid + it * 256, kr = idx / SEGS, sg = idx % SEGS;
                uint32_t d = base + A_TOT + kr * PB + sg * 16;
                long long o = (long long)(k0 + kr) * ldb + n0 + sg * 8;
                CP16(d, Bh_ + o);
                if (BP) CP16(d + B_SZ, Bl_ + o);
            }
        }
    };

    float acc[MI][NI][4] = {};

    const int nch = K / BK;
    stage_in(0, sb0);
    CP_COMMIT();

    for (int c = 0; c < nch; ++c) {
        if (c + 1 < nch) stage_in(c + 1, sb0 + ((c + 1) & 1) * STAGE);
        CP_COMMIT();
        CP_WAIT1();
        __syncthreads();

        const uint32_t ab = sb0 + (c & 1) * STAGE;
        const uint32_t bb = ab + A_TOT;
#pragma unroll
        for (int ks = 0; ks < 2; ++ks) {
            const int kk = ks * 16;
            uint32_t bh[NI][2], bl[NI][2];
            if (TB == 1) {
                // paired loads: one ldsm_x4 covers ni and ni+1
#pragma unroll
                for (int ni = 0; ni < NI; ni += 2) {
                    uint32_t addr = bb + (n_base + ni * 8 + (lane & 7) + ((lane >> 4) * 8)) * 80
                                       + (kk + ((lane >> 3) & 1) * 8) * 2;
                    uint32_t quad[4];
                    ldsm_x4(quad, addr);
                    bh[ni][0] = quad[0]; bh[ni][1] = quad[1];
                    bh[ni + 1][0] = quad[2]; bh[ni + 1][1] = quad[3];
                    if (BP) {
                        ldsm_x4(quad, addr + B_SZ);
                        bl[ni][0] = quad[0]; bl[ni][1] = quad[1];
                        bl[ni + 1][0] = quad[2]; bl[ni + 1][1] = quad[3];
                    }
                }
            } else {
#pragma unroll
                for (int ni = 0; ni < NI; ++ni) {
                    uint32_t addr = bb + (kk + (lane & 15)) * PB + (n_base + ni * 8) * 2;
                    ldsm_x2_t(bh[ni], addr);
                    if (BP) ldsm_x2_t(bl[ni], addr + B_SZ);
                }
            }
#pragma unroll
            for (int mi = 0; mi < MI; ++mi) {
                uint32_t ah[4], al[4], ad;
                if (TA == 0) {
                    ad = ab + (m_base + mi * 16 + (lane & 15)) * 80 + (kk + (lane >> 4) * 8) * 2;
                    ldsm_x4(ah, ad);
                    if (AP) ldsm_x4(al, ad + A_SZ);
                } else {
                    ad = ab + (kk + (lane & 7) + (lane >> 4) * 8) * 272
                            + (m_base + mi * 16 + ((lane >> 3) & 1) * 8) * 2;
                    ldsm_x4_t(ah, ad);
                    if (AP) ldsm_x4_t(al, ad + A_SZ);
                }
#pragma unroll
                for (int ni = 0; ni < NI; ++ni) {
                    mma16816(acc[mi][ni], ah, bh[ni]);
                    if (BP) mma16816(acc[mi][ni], ah, bl[ni]);
                    if (AP) mma16816(acc[mi][ni], al, bh[ni]);
                }
            }
        }
        __syncthreads();
    }

    // ---- epilogue ----
    if (OUT == 3) {
        float* rs = rsum + (long long)blockIdx.z * ((long long)gridDim.y * BM);
#pragma unroll
        for (int mi = 0; mi < MI; ++mi) {
            int m = m0 + m_base + mi * 16 + (lane >> 2);
            float ra = 0.f, rb = 0.f;
#pragma unroll
            for (int ni = 0; ni < NI; ++ni) {
                int n = n0 + n_base + ni * 8 + 2 * (lane & 3);
                float e0 = fexp(acc[mi][ni][0] * alpha);
                float e1 = fexp(acc[mi][ni][1] * alpha);
                float e2 = fexp(acc[mi][ni][2] * alpha);
                float e3 = fexp(acc[mi][ni][3] * alpha);
                *reinterpret_cast<uint32_t*>(&Ch[(long long)m * ldc + n]) = pack_bf2(e0, e1);
                *reinterpret_cast<uint32_t*>(&Ch[(long long)(m + 8) * ldc + n]) = pack_bf2(e2, e3);
                ra += e0 + e1;
                rb += e2 + e3;
            }
            ra += __shfl_xor_sync(0xffffffffu, ra, 1);
            ra += __shfl_xor_sync(0xffffffffu, ra, 2);
            rb += __shfl_xor_sync(0xffffffffu, rb, 1);
            rb += __shfl_xor_sync(0xffffffffu, rb, 2);
            if ((lane & 3) == 0) {
                atomicAdd(&rs[m], ra);
                atomicAdd(&rs[m + 8], rb);
            }
        }
        return;
    }

#pragma unroll
    for (int mi = 0; mi < MI; ++mi) {
#pragma unroll
        for (int ni = 0; ni < NI; ++ni) {
            int m = m0 + m_base + mi * 16 + (lane >> 2);
            int n = n0 + n_base + ni * 8 + 2 * (lane & 3);
            float v0 = acc[mi][ni][0] * alpha, v1 = acc[mi][ni][1] * alpha;
            float v2 = acc[mi][ni][2] * alpha, v3 = acc[mi][ni][3] * alpha;
            if (BIAS == 1) { float b = bias1[m], bb8 = bias1[m + 8]; v0 += b; v1 += b; v2 += bb8; v3 += bb8; }
            if (BIAS == 2) { float b = bias1[n], bb1 = bias1[n + 1]; v0 += b; v1 += bb1; v2 += b; v3 += bb1; }
            if (BIAS == 3) {
                float c0 = b2[n], c1 = b2[n + 1];
                float bm = bias1[m], bm8 = bias1[m + 8];
                v0 += bm * c0; v1 += bm * c1; v2 += bm8 * c0; v3 += bm8 * c1;
            }
            if (OUT == 0) {
                *reinterpret_cast<float2*>(&Cf[(long long)m * ldc + n]) = make_float2(v0, v1);
                *reinterpret_cast<float2*>(&Cf[(long long)(m + 8) * ldc + n]) = make_float2(v2, v3);
            } else if (OUT == 4) {
                int col = n & (CDIM - 1);
                *reinterpret_cast<uint32_t*>(&Ch[(long long)m * CDIM + col]) = pack_bf2(v0, v1);
                *reinterpret_cast<uint32_t*>(&Ch[(long long)(m + 8) * CDIM + col]) = pack_bf2(v2, v3);
            } else {
                *reinterpret_cast<uint32_t*>(&Ch[(long long)m * ldc + n]) = pack_bf2(v0, v1);
                *reinterpret_cast<uint32_t*>(&Ch[(long long)(m + 8) * ldc + n]) = pack_bf2(v2, v3);
            }
        }
    }
}

// ---------------------------------------------------------------------------
// Attn helpers
// ---------------------------------------------------------------------------
// vh[b,q,c] *= 1/rs[b, c/64, q]  (reciprocal inline; rs stays L2-hot)
__global__ void scale_v(__nv_bfloat16* __restrict__ v, const float* __restrict__ rs)
{
    int i = blockIdx.x * 256 + threadIdx.x;          // word index, E_X/2 total
    int e0 = 2 * i;
    int c = e0 & (CDIM - 1);
    int bq = e0 >> 10;
    int b = bq >> 11, q = bq & (SEQ - 1);
    int h = c >> 6;
    float iz = __fdividef(1.0f, rs[(((long long)b * NH + h) << 11) + q]);
    uint32_t u = reinterpret_cast<uint32_t*>(v)[i];
    float x0 = __uint_as_float(u << 16) * iz;
    float x1 = __uint_as_float(u & 0xffff0000u) * iz;
    reinterpret_cast<uint32_t*>(v)[i] = pack_bf2(x0, x1);
}

// ---------------------------------------------------------------------------
// Analytic-S helper chain (parallel, atomic-merged)
// ---------------------------------------------------------------------------
__global__ void zero_ws(float* __restrict__ W1, float* __restrict__ sxh,
                        float* __restrict__ rs)
{
    int i = blockIdx.x * blockDim.x + threadIdx.x;
    if (i <= SEQ) W1[i] = 0.f;
    if (i < NB_ * CDIM) sxh[i] = 0.f;
    if (i < (int)N_RS) rs[i] = 0.f;
}

__global__ void sum_bias(const float* __restrict__ b, float* __restrict__ W1)
{
    __shared__ float red[256];
    float acc = 0.f;
    for (int i = threadIdx.x; i < SEQ; i += 256) acc += b[i];
    red[threadIdx.x] = acc;
    __syncthreads();
    for (int o = 128; o; o >>= 1) {
        if (threadIdx.x < o) red[threadIdx.x] += red[threadIdx.x + o];
        __syncthreads();
    }
    if (threadIdx.x == 0) W1[SEQ] = red[0];
}

__global__ void add_bsum(float* __restrict__ sxh, const float* __restrict__ W1)
{
    int i = blockIdx.x * blockDim.x + threadIdx.x;
    if (i < NB_ * CDIM) sxh[i] += W1[SEQ];
}

__global__ void s_from_xh(const float* __restrict__ sxh,
                          const float* __restrict__ wv,
                          const float* __restrict__ bv,
                          float* __restrict__ s)
{
    int o = blockIdx.x * 8 + (threadIdx.x >> 5);
    int lane = threadIdx.x & 31;
    int b = o >> 10, cp = o & (CDIM - 1);
    const float* xr = sxh + (long long)b * CDIM;
    const float* wr = wv + (long long)cp * CDIM;
    float acc = 0.f;
#pragma unroll 8
    for (int c = lane; c < CDIM; c += 32) acc += xr[c] * wr[c];
#pragma unroll
    for (int off = 16; off; off >>= 1) acc += __shfl_xor_sync(0xffffffffu, acc, off);
    if (lane == 0) s[o] = acc + (float)SEQ * bv[cp];
}

// ---------------------------------------------------------------------------
// Launch
// ---------------------------------------------------------------------------
extern "C" void kernel_launch(void* const* d_in, const int* in_sizes, int n_in,
                              void* d_out, int out_size)
{
    const float* x      = (const float*)d_in[0];
    const float* w_hseq = (const float*)d_in[1];
    const float* b_hseq = (const float*)d_in[2];
    const float* wq     = (const float*)d_in[3];
    const float* bq     = (const float*)d_in[4];
    const float* wk     = (const float*)d_in[5];
    const float* bk     = (const float*)d_in[6];
    const float* wv     = (const float*)d_in[7];
    const float* bv     = (const float*)d_in[8];
    const float* w_oseq = (const float*)d_in[9];
    const float* b_oseq = (const float*)d_in[10];
    float* out = (float*)d_out;

    __nv_bfloat16 *xbh, *whh, *wqkvh, *woh, *xhh, *qkv3, *zh, *attn;
    float *sv, *sxh, *W1, *rs, *bqkv;
    cudaGetSymbolAddress((void**)&xbh,   g_xb_h);
    cudaGetSymbolAddress((void**)&whh,   g_whs_h);
    cudaGetSymbolAddress((void**)&wqkvh, g_wqkv_h);
    cudaGetSymbolAddress((void**)&woh,   g_wo_h);
    cudaGetSymbolAddress((void**)&xhh,   g_xh_h);
    cudaGetSymbolAddress((void**)&qkv3,  g_qkv3);
    cudaGetSymbolAddress((void**)&zh,    g_z_h);
    cudaGetSymbolAddress((void**)&attn,  g_attn);
    cudaGetSymbolAddress((void**)&bqkv,  g_bqkv);
    cudaGetSymbolAddress((void**)&rs,    g_rs);
    cudaGetSymbolAddress((void**)&W1,    g_W1);
    cudaGetSymbolAddress((void**)&sxh,   g_sxh);
    cudaGetSymbolAddress((void**)&sv,    g_s);

    __nv_bfloat16* qh = qkv3;
    __nv_bfloat16* kh = qkv3 + E_X;
    __nv_bfloat16* vh = qkv3 + 2 * E_X;

    const long long sBT = (long long)SEQ * CDIM;
    const long long sAh_ = (long long)SEQ * SEQ;
    const long long sAb = (long long)NH * SEQ * SEQ;

    // smem: 2 stages of (A_TOT + B_TOT), BK=32
    const int SM_A = 2 * (10240 + 8704);   // 37888  <0,0,1,128,2,0,0>
    const int SM_B = 2 * (10240 + 10240);  // 40960  <0,1,2,128,4>/<C>
    const int SM_E = 2 * (8704 + 4608);    // 26624  <1,0,0,64,2,0,0>
    const int SM_F = 2 * (10240 + 8704);   // 37888  <0,0,3,128,0,0,0>

    cudaFuncSetAttribute(tgemm<0, 0, 1, 128, 2, 0, 0>, cudaFuncAttributeMaxDynamicSharedMemorySize, SM_A);
    cudaFuncSetAttribute(tgemm<0, 1, 2, 128, 4, 0, 0>, cudaFuncAttributeMaxDynamicSharedMemorySize, SM_B);
    cudaFuncSetAttribute(tgemm<0, 1, 0, 128, 3, 0, 0>, cudaFuncAttributeMaxDynamicSharedMemorySize, SM_B);
    cudaFuncSetAttribute(tgemm<1, 0, 0, 64, 2, 0, 0>,  cudaFuncAttributeMaxDynamicSharedMemorySize, SM_E);
    cudaFuncSetAttribute(tgemm<0, 0, 3, 128, 0, 0, 0>, cudaFuncAttributeMaxDynamicSharedMemorySize, SM_F);

    // Weight converts (independent)
    convert_hi<<<(int)(E_W / 4 / 256), 256>>>(wq, wqkvh, (int)(E_W / 4));
    convert_hi<<<(int)(E_W / 4 / 256), 256>>>(wk, wqkvh + E_W, (int)(E_W / 4));
    convert_hi<<<(int)(E_W / 4 / 256), 256>>>(wv, wqkvh + 2 * E_W, (int)(E_W / 4));
    convert_hi<<<(int)(E_WS / 4 / 256), 256>>>(w_oseq, woh, (int)(E_WS / 4));

    // S chain + fused converts (W1 before x-convert)
    zero_ws<<<(int)(N_RS / 256), 256>>>(W1, sxh, rs);
    convert_rowsum_w<<<dim3(SEQ / 256, SEQ / 128), 256>>>(w_hseq, whh, W1);
    sum_bias<<<1, 256>>>(b_hseq, W1);
    convert_x_sxh<<<dim3((NB_ * CDIM) / 256, SEQ / 128), 256>>>(x, W1, xbh, sxh);
    add_bsum<<<(NB_ * CDIM + 255) / 256, 256>>>(sxh, W1);
    s_from_xh<<<(NB_ * CDIM) / 8, 256>>>(sxh, wv, bv, sv);
    concat_bias<<<12, 256>>>(bq, bk, bv, bqkv);

    // Stage A: xh = w_hseq @ x + b_hseq  (1-pass, hi-only out)
    tgemm<0, 0, 1, 128, 2, 0, 0><<<dim3(CDIM / 128, SEQ / 128, NB_), 256, SM_A>>>(
        whh, nullptr, xbh, nullptr, nullptr, xhh, nullptr,
        SEQ, CDIM, CDIM, 0, 0, sBT, 0, sBT, 0, 1,
        b_hseq, nullptr, 0, 0, 1.0f, SEQ, nullptr);

    // Stage B (merged QKV, dense split outputs): q|k|v = xh @ wqkv^T + bqkv
    tgemm<0, 1, 2, 128, 4, 0, 0><<<dim3(3 * CDIM / 128, (NB_ * SEQ) / 128, 1), 256, SM_B>>>(
        xhh, nullptr, wqkvh, nullptr, nullptr, qkv3, nullptr,
        CDIM, CDIM, CDIM, 0, 0, 0, 0, 0, 0, 1,
        bqkv, nullptr, 0, 0, 1.0f, CDIM, nullptr);

    // Stage C: e = exp((1/8) q.k) -> bf16, + row sums (atomic)
    tgemm<0, 1, 0, 128, 3, 0, 0><<<dim3(SEQ / 128, SEQ / 128, NB_ * NH), 256, SM_B>>>(
        qh, nullptr, kh, nullptr, nullptr, attn, nullptr,
        CDIM, CDIM, SEQ, sBT, HD, sBT, HD, sAb, sAh_, NH,
        nullptr, nullptr, 0, 0, 0.125f, HD, rs);

    // Fold softmax normalization into V:  v' = v / Zrow
    scale_v<<<(int)(E_X / 2 / 256), 256>>>(vh, rs);

    // Stage E: Z[b, kj, h*64+d] = sum_q e[q,kj] * v'[q, h*64+d]  (dense Z)
    tgemm<1, 0, 0, 64, 2, 0, 0><<<dim3(1, SEQ / 128, NB_ * NH), 256, SM_E>>>(
        attn, nullptr, vh, nullptr, nullptr, zh, nullptr,
        SEQ, CDIM, CDIM, sAb, sAh_, sBT, HD, sBT, HD, NH,
        nullptr, nullptr, 0, 0, 1.0f, SEQ, nullptr);

    // Stage F: out[b] = wo @ Z[b] + b_oseq (x) S[b]   (batch-2 dense GEMM)
    tgemm<0, 0, 3, 128, 0, 0, 0><<<dim3(CDIM / 128, SEQ / 128, NB_), 256, SM_F>>>(
        woh, nullptr, zh, nullptr, out, nullptr, nullptr,
        SEQ, CDIM, CDIM, 0, 0, sBT, 0, sBT, 0, 1,
        b_oseq, sv, CDIM, 0, 1.0f, SEQ, nullptr);
}